// round 2
// baseline (speedup 1.0000x reference)
#include <cuda_runtime.h>
#include <cuda_bf16.h>

#define N_NODES 50000
#define N_EDGES 1600000
#define C_OUT   256

// ---------------- scratch (static device globals; allocation-free) ----------
__device__ int   g_is64;
__device__ int   g_src[N_EDGES];
__device__ int   g_dst[N_EDGES];
__device__ float g_ew[N_EDGES];
__device__ int   g_srcS[N_EDGES];
__device__ float g_ewS[N_EDGES];
__device__ int   g_deg[N_NODES];
__device__ int   g_rowoff[N_NODES + 1];
__device__ int   g_cursor[N_NODES];
__device__ float g_agg[(size_t)N_NODES * C_OUT];
__device__ float g_h[(size_t)N_NODES * C_OUT];

// ---------------- int64-vs-int32 edge_index detection -----------------------
__global__ void detect_kernel(const int* __restrict__ ei_words) {
    __shared__ int nz;
    if (threadIdx.x == 0) nz = 0;
    __syncthreads();
    if (ei_words[2 * threadIdx.x + 1] != 0) atomicOr(&nz, 1);
    __syncthreads();
    if (threadIdx.x == 0) g_is64 = (nz == 0) ? 1 : 0;
}

__global__ void zero_deg_kernel() {
    int i = blockIdx.x * blockDim.x + threadIdx.x;
    if (i < N_NODES) g_deg[i] = 0;
}

// decode edge_index, compute ew = mean(edge_attr, -1), histogram dst degrees
__global__ void build_edges_kernel(const int* __restrict__ ei,
                                   const float* __restrict__ ea) {
    int e = blockIdx.x * blockDim.x + threadIdx.x;
    if (e >= N_EDGES) return;
    int s, d;
    if (g_is64) {
        s = ei[2 * (size_t)e];
        d = ei[2 * (size_t)N_EDGES + 2 * (size_t)e];
    } else {
        s = ei[e];
        d = ei[N_EDGES + e];
    }
    g_src[e] = s;
    g_dst[e] = d;
    const float4* a4 = (const float4*)(ea + (size_t)e * 8);
    float4 u = a4[0];
    float4 v = a4[1];
    g_ew[e] = (u.x + u.y + u.z + u.w + v.x + v.y + v.z + v.w) * 0.125f;
    atomicAdd(&g_deg[d], 1);
}

// chunk-per-thread exclusive scan: local sum -> block scan -> local prefix.
// One pass over data, 2 syncs total (vs 49 x ~20 block-wide passes before).
__global__ void scan_kernel() {
    const int CH = (N_NODES + 1023) / 1024;  // 49
    int tid = threadIdx.x;
    int s = tid * CH;
    int e = min(s + CH, N_NODES);
    if (s > N_NODES) s = N_NODES;

    int sum = 0;
    for (int i = s; i < e; i++) sum += g_deg[i];

    __shared__ int warpsum[32];
    int lane = tid & 31, wid = tid >> 5;
    int v = sum;
#pragma unroll
    for (int o = 1; o < 32; o <<= 1) {
        int t = __shfl_up_sync(~0u, v, o);
        if (lane >= o) v += t;
    }
    if (lane == 31) warpsum[wid] = v;
    __syncthreads();
    if (wid == 0) {
        int w = warpsum[lane];
#pragma unroll
        for (int o = 1; o < 32; o <<= 1) {
            int t = __shfl_up_sync(~0u, w, o);
            if (lane >= o) w += t;
        }
        warpsum[lane] = w;
    }
    __syncthreads();

    int run = (v - sum) + (wid > 0 ? warpsum[wid - 1] : 0);  // exclusive base
    for (int i = s; i < e; i++) {
        int d = g_deg[i];
        g_rowoff[i] = run;
        g_cursor[i] = run;
        run += d;
    }
    if (tid == 1023) g_rowoff[N_NODES] = run;
}

// scatter edges into CSR buckets (sorted by dst)
__global__ void fill_kernel() {
    int e = blockIdx.x * blockDim.x + threadIdx.x;
    if (e >= N_EDGES) return;
    int d = g_dst[e];
    int p = atomicAdd(&g_cursor[d], 1);
    g_srcS[p] = g_src[e];
    g_ewS[p] = g_ew[e];
}

// ---------------- gather-aggregate: out[i] = sum_{e: dst=i} in[src_e] * w_e --
template <int C, bool USE_W>
__global__ void gather_kernel(const float* __restrict__ in,
                              float* __restrict__ out) {
    constexpr int L = C / 4;        // lanes per node
    constexpr int G = 256 / L;      // nodes per 256-thread block
    int grp  = threadIdx.x / L;
    int lane = threadIdx.x % L;
    int node = blockIdx.x * G + grp;
    if (node >= N_NODES) return;

    int e0 = g_rowoff[node];
    int e1 = g_rowoff[node + 1];
    const float4* in4 = (const float4*)in;
    float4 acc = make_float4(0.f, 0.f, 0.f, 0.f);

    int e = e0;
    for (; e + 4 <= e1; e += 4) {
        int s0 = g_srcS[e], s1 = g_srcS[e + 1];
        int s2 = g_srcS[e + 2], s3 = g_srcS[e + 3];
        float w0 = USE_W ? g_ewS[e] : 1.0f;
        float w1 = USE_W ? g_ewS[e + 1] : 1.0f;
        float w2 = USE_W ? g_ewS[e + 2] : 1.0f;
        float w3 = USE_W ? g_ewS[e + 3] : 1.0f;
        float4 v0 = in4[(size_t)s0 * L + lane];
        float4 v1 = in4[(size_t)s1 * L + lane];
        float4 v2 = in4[(size_t)s2 * L + lane];
        float4 v3 = in4[(size_t)s3 * L + lane];
        acc.x = fmaf(v0.x, w0, acc.x); acc.y = fmaf(v0.y, w0, acc.y);
        acc.z = fmaf(v0.z, w0, acc.z); acc.w = fmaf(v0.w, w0, acc.w);
        acc.x = fmaf(v1.x, w1, acc.x); acc.y = fmaf(v1.y, w1, acc.y);
        acc.z = fmaf(v1.z, w1, acc.z); acc.w = fmaf(v1.w, w1, acc.w);
        acc.x = fmaf(v2.x, w2, acc.x); acc.y = fmaf(v2.y, w2, acc.y);
        acc.z = fmaf(v2.z, w2, acc.z); acc.w = fmaf(v2.w, w2, acc.w);
        acc.x = fmaf(v3.x, w3, acc.x); acc.y = fmaf(v3.y, w3, acc.y);
        acc.z = fmaf(v3.z, w3, acc.z); acc.w = fmaf(v3.w, w3, acc.w);
    }
    for (; e < e1; e++) {
        int sa = g_srcS[e];
        float wa = USE_W ? g_ewS[e] : 1.0f;
        float4 va = in4[(size_t)sa * L + lane];
        acc.x = fmaf(va.x, wa, acc.x); acc.y = fmaf(va.y, wa, acc.y);
        acc.z = fmaf(va.z, wa, acc.z); acc.w = fmaf(va.w, wa, acc.w);
    }
    ((float4*)out)[(size_t)node * L + lane] = acc;
}

// ---------------- GEMM: out[M,256] = A[M,K] @ W[256,K]^T + epilogue ---------
// BM=BN=128, BK=16, 256 threads, 8x8 register tile, double-buffered smem.
template <int K, bool BN_RELU>
__global__ __launch_bounds__(256, 2)
void gemm_kernel(const float* __restrict__ A,
                 const float* __restrict__ W,
                 const float* __restrict__ bias,
                 const float* __restrict__ gam,
                 const float* __restrict__ bet,
                 const float* __restrict__ mu,
                 const float* __restrict__ var,
                 float* __restrict__ out) {
    constexpr int BM = 128, BN = 128, BK = 16;
    constexpr int NT = K / BK;  // k-tiles
    __shared__ float As[2][BK][BM + 4];
    __shared__ float Bs[2][BK][BN + 4];

    int m0 = blockIdx.x * BM;
    int n0 = blockIdx.y * BN;
    int t = threadIdx.x;

    // loader mapping: each thread loads 2 float4s of A and 2 of B per tile
    int lr = t >> 1;            // 0..127 : row within tile
    int lk = (t & 1) * 8;       // 0 or 8 : k offset (two float4s: lk, lk+4)

    // compute mapping: 8x8 per thread
    int tx = t & 15;            // n group: cols tx*8 .. tx*8+7
    int ty = t >> 4;            // m group: rows ty*8 .. ty*8+7

    float acc[8][8];
#pragma unroll
    for (int i = 0; i < 8; i++)
#pragma unroll
        for (int j = 0; j < 8; j++) acc[i][j] = 0.f;

    // ---- load tile 0 into buffer 0 ----
    {
        int row = m0 + lr;
        float4 a0 = make_float4(0.f, 0.f, 0.f, 0.f), a1 = a0;
        if (row < N_NODES) {
            const float* ap = A + (size_t)row * K + lk;
            a0 = *(const float4*)(ap);
            a1 = *(const float4*)(ap + 4);
        }
        const float* wp = W + (size_t)(n0 + lr) * K + lk;
        float4 b0 = *(const float4*)(wp);
        float4 b1 = *(const float4*)(wp + 4);
        As[0][lk + 0][lr] = a0.x; As[0][lk + 1][lr] = a0.y;
        As[0][lk + 2][lr] = a0.z; As[0][lk + 3][lr] = a0.w;
        As[0][lk + 4][lr] = a1.x; As[0][lk + 5][lr] = a1.y;
        As[0][lk + 6][lr] = a1.z; As[0][lk + 7][lr] = a1.w;
        Bs[0][lk + 0][lr] = b0.x; Bs[0][lk + 1][lr] = b0.y;
        Bs[0][lk + 2][lr] = b0.z; Bs[0][lk + 3][lr] = b0.w;
        Bs[0][lk + 4][lr] = b1.x; Bs[0][lk + 5][lr] = b1.y;
        Bs[0][lk + 6][lr] = b1.z; Bs[0][lk + 7][lr] = b1.w;
    }
    __syncthreads();

    int buf = 0;
#pragma unroll
    for (int kt = 0; kt < NT; kt++) {
        // prefetch next tile into registers
        float4 pa0, pa1, pb0, pb1;
        bool has_next = (kt + 1 < NT);
        if (has_next) {
            int k0 = (kt + 1) * BK;
            int row = m0 + lr;
            pa0 = make_float4(0.f, 0.f, 0.f, 0.f); pa1 = pa0;
            if (row < N_NODES) {
                const float* ap = A + (size_t)row * K + k0 + lk;
                pa0 = *(const float4*)(ap);
                pa1 = *(const float4*)(ap + 4);
            }
            const float* wp = W + (size_t)(n0 + lr) * K + k0 + lk;
            pb0 = *(const float4*)(wp);
            pb1 = *(const float4*)(wp + 4);
        }

        // compute on current buffer
#pragma unroll
        for (int k = 0; k < BK; k++) {
            float4 a0 = *(const float4*)&As[buf][k][ty * 8];
            float4 a1 = *(const float4*)&As[buf][k][ty * 8 + 4];
            float4 b0 = *(const float4*)&Bs[buf][k][tx * 8];
            float4 b1 = *(const float4*)&Bs[buf][k][tx * 8 + 4];
            float ar[8] = {a0.x, a0.y, a0.z, a0.w, a1.x, a1.y, a1.z, a1.w};
            float br[8] = {b0.x, b0.y, b0.z, b0.w, b1.x, b1.y, b1.z, b1.w};
#pragma unroll
            for (int i = 0; i < 8; i++)
#pragma unroll
                for (int j = 0; j < 8; j++)
                    acc[i][j] = fmaf(ar[i], br[j], acc[i][j]);
        }

        if (has_next) {
            int nb = buf ^ 1;
            As[nb][lk + 0][lr] = pa0.x; As[nb][lk + 1][lr] = pa0.y;
            As[nb][lk + 2][lr] = pa0.z; As[nb][lk + 3][lr] = pa0.w;
            As[nb][lk + 4][lr] = pa1.x; As[nb][lk + 5][lr] = pa1.y;
            As[nb][lk + 6][lr] = pa1.z; As[nb][lk + 7][lr] = pa1.w;
            Bs[nb][lk + 0][lr] = pb0.x; Bs[nb][lk + 1][lr] = pb0.y;
            Bs[nb][lk + 2][lr] = pb0.z; Bs[nb][lk + 3][lr] = pb0.w;
            Bs[nb][lk + 4][lr] = pb1.x; Bs[nb][lk + 5][lr] = pb1.y;
            Bs[nb][lk + 6][lr] = pb1.z; Bs[nb][lk + 7][lr] = pb1.w;
            __syncthreads();
            buf = nb;
        }
    }

    // ---- epilogue: +bias, optional BN(eval)+ReLU, 2x float4 stores/row ----
    int nbase = n0 + tx * 8;
    float bb[8], ss[8], tt[8];
#pragma unroll
    for (int j = 0; j < 8; j++) {
        bb[j] = bias[nbase + j];
        if (BN_RELU) {
            float inv = gam[nbase + j] * rsqrtf(var[nbase + j] + 1e-5f);
            ss[j] = inv;
            tt[j] = bet[nbase + j] - mu[nbase + j] * inv;
        }
    }
#pragma unroll
    for (int i = 0; i < 8; i++) {
        int m = m0 + ty * 8 + i;
        if (m < N_NODES) {
            float z[8];
#pragma unroll
            for (int j = 0; j < 8; j++) {
                float v = acc[i][j] + bb[j];
                if (BN_RELU) v = fmaxf(fmaf(v, ss[j], tt[j]), 0.f);
                z[j] = v;
            }
            float* op = out + (size_t)m * C_OUT + nbase;
            *(float4*)(op)     = make_float4(z[0], z[1], z[2], z[3]);
            *(float4*)(op + 4) = make_float4(z[4], z[5], z[6], z[7]);
        }
    }
}

// ---------------- launch ----------------------------------------------------
extern "C" void kernel_launch(void* const* d_in, const int* in_sizes, int n_in,
                              void* d_out, int out_size) {
    const float* x   = (const float*)d_in[0];
    const int*   ei  = (const int*)d_in[1];
    const float* ea  = (const float*)d_in[2];
    const float* W1  = (const float*)d_in[3];
    const float* b1  = (const float*)d_in[4];
    const float* g1  = (const float*)d_in[5];
    const float* be1 = (const float*)d_in[6];
    const float* m1  = (const float*)d_in[7];
    const float* v1  = (const float*)d_in[8];
    const float* W2  = (const float*)d_in[9];
    const float* b2  = (const float*)d_in[10];
    const float* g2  = (const float*)d_in[11];
    const float* be2 = (const float*)d_in[12];
    const float* m2  = (const float*)d_in[13];
    const float* v2  = (const float*)d_in[14];
    const float* W3  = (const float*)d_in[15];
    const float* b3  = (const float*)d_in[16];
    float* out = (float*)d_out;

    void *p_agg, *p_h;
    cudaGetSymbolAddress(&p_agg, g_agg);
    cudaGetSymbolAddress(&p_h, g_h);
    float* agg = (float*)p_agg;
    float* h   = (float*)p_h;

    // ---- CSR build (once, reused by all 3 layers) ----
    detect_kernel<<<1, 64>>>(ei);
    zero_deg_kernel<<<(N_NODES + 255) / 256, 256>>>();
    build_edges_kernel<<<(N_EDGES + 255) / 256, 256>>>(ei, ea);
    scan_kernel<<<1, 1024>>>();
    fill_kernel<<<(N_EDGES + 255) / 256, 256>>>();

    dim3 ggrid((N_NODES + 127) / 128, 2);  // 391 x 2, BM=BN=128

    // ---- layer 1: aggregate x (C=128), GEMM K=128 + BN1 + ReLU ----
    gather_kernel<128, true><<<(N_NODES + 7) / 8, 256>>>(x, agg);
    gemm_kernel<128, true><<<ggrid, 256>>>(agg, W1, b1, g1, be1, m1, v1, h);

    // ---- layer 2: aggregate h (C=256), GEMM K=256 + BN2 + ReLU ----
    gather_kernel<256, true><<<(N_NODES + 3) / 4, 256>>>(h, agg);
    gemm_kernel<256, true><<<ggrid, 256>>>(agg, W2, b2, g2, be2, m2, v2, h);

    // ---- layer 3: aggregate h (C=256, no edge weight), GEMM K=256 + bias ----
    gather_kernel<256, false><<<(N_NODES + 3) / 4, 256>>>(h, agg);
    gemm_kernel<256, false><<<ggrid, 256>>>(agg, W3, b3, nullptr, nullptr,
                                            nullptr, nullptr, out);
}

// round 3
// speedup vs baseline: 1.2038x; 1.2038x over previous
#include <cuda_runtime.h>
#include <cuda_bf16.h>

#define N_NODES 50000
#define N_EDGES 1600000
#define C_OUT   256
#define SCAN_BLOCKS 196   // ceil(50000/256)

// ---------------- scratch (static device globals; allocation-free) ----------
__device__ int   g_is64;
__device__ int   g_src[N_EDGES];
__device__ int   g_dst[N_EDGES];
__device__ float g_ew[N_EDGES];
__device__ int   g_srcS[N_EDGES];
__device__ float g_ewS[N_EDGES];
__device__ int   g_deg[N_NODES];
__device__ int   g_blkoff[SCAN_BLOCKS];
__device__ int   g_rowoff[N_NODES + 1];
__device__ int   g_cursor[N_NODES];
__device__ float g_agg[(size_t)N_NODES * C_OUT];
__device__ float g_h[(size_t)N_NODES * C_OUT];

// ---------------- int64-vs-int32 edge_index detection -----------------------
__global__ void detect_kernel(const int* __restrict__ ei_words) {
    __shared__ int nz;
    if (threadIdx.x == 0) nz = 0;
    __syncthreads();
    if (ei_words[2 * threadIdx.x + 1] != 0) atomicOr(&nz, 1);
    __syncthreads();
    if (threadIdx.x == 0) g_is64 = (nz == 0) ? 1 : 0;
}

// decode edge_index, compute ew = mean(edge_attr, -1), histogram dst degrees
__global__ void build_edges_kernel(const int* __restrict__ ei,
                                   const float* __restrict__ ea) {
    int e = blockIdx.x * blockDim.x + threadIdx.x;
    if (e >= N_EDGES) return;
    int s, d;
    if (g_is64) {
        s = ei[2 * (size_t)e];
        d = ei[2 * (size_t)N_EDGES + 2 * (size_t)e];
    } else {
        s = ei[e];
        d = ei[N_EDGES + e];
    }
    g_src[e] = s;
    g_dst[e] = d;
    const float4* a4 = (const float4*)(ea + (size_t)e * 8);
    float4 u = a4[0];
    float4 v = a4[1];
    g_ew[e] = (u.x + u.y + u.z + u.w + v.x + v.y + v.z + v.w) * 0.125f;
    atomicAdd(&g_deg[d], 1);
}

// ---------------- decoupled 3-phase exclusive scan ---------------------------
// phase 1: per-block sums (196 blocks x 256 threads, 1 node/thread)
__global__ void scan_p1_kernel() {
    int i = blockIdx.x * 256 + threadIdx.x;
    int v = (i < N_NODES) ? g_deg[i] : 0;
#pragma unroll
    for (int o = 16; o > 0; o >>= 1) v += __shfl_down_sync(~0u, v, o);
    __shared__ int ws[8];
    int lane = threadIdx.x & 31, wid = threadIdx.x >> 5;
    if (lane == 0) ws[wid] = v;
    __syncthreads();
    if (threadIdx.x == 0) {
        int s = 0;
#pragma unroll
        for (int w = 0; w < 8; w++) s += ws[w];
        g_blkoff[blockIdx.x] = s;
    }
}

// phase 2: one block scans the 196 block sums (exclusive, in place)
__global__ void scan_p2_kernel() {
    int tid = threadIdx.x;  // 256 threads
    int v = (tid < SCAN_BLOCKS) ? g_blkoff[tid] : 0;
    int lane = tid & 31, wid = tid >> 5;
    int x = v;
#pragma unroll
    for (int o = 1; o < 32; o <<= 1) {
        int t = __shfl_up_sync(~0u, x, o);
        if (lane >= o) x += t;
    }
    __shared__ int ws[8];
    if (lane == 31) ws[wid] = x;
    __syncthreads();
    if (wid == 0 && lane < 8) {
        int w = ws[lane];
#pragma unroll
        for (int o = 1; o < 8; o <<= 1) {
            int t = __shfl_up_sync(0xffu, w, o);
            if (lane >= o) w += t;
        }
        ws[lane] = w;
    }
    __syncthreads();
    int excl = (x - v) + (wid > 0 ? ws[wid - 1] : 0);
    if (tid < SCAN_BLOCKS) g_blkoff[tid] = excl;
    if (tid == 0) g_rowoff[N_NODES] = N_EDGES;
}

// phase 3: block-local exclusive scan + block offset -> rowoff, cursor
__global__ void scan_p3_kernel() {
    int i = blockIdx.x * 256 + threadIdx.x;
    int v = (i < N_NODES) ? g_deg[i] : 0;
    int lane = threadIdx.x & 31, wid = threadIdx.x >> 5;
    int x = v;
#pragma unroll
    for (int o = 1; o < 32; o <<= 1) {
        int t = __shfl_up_sync(~0u, x, o);
        if (lane >= o) x += t;
    }
    __shared__ int ws[8];
    if (lane == 31) ws[wid] = x;
    __syncthreads();
    if (wid == 0 && lane < 8) {
        int w = ws[lane];
#pragma unroll
        for (int o = 1; o < 8; o <<= 1) {
            int t = __shfl_up_sync(0xffu, w, o);
            if (lane >= o) w += t;
        }
        ws[lane] = w;
    }
    __syncthreads();
    int excl = (x - v) + (wid > 0 ? ws[wid - 1] : 0) + g_blkoff[blockIdx.x];
    if (i < N_NODES) {
        g_rowoff[i] = excl;
        g_cursor[i] = excl;
    }
}

// scatter edges into CSR buckets (sorted by dst)
__global__ void fill_kernel() {
    int e = blockIdx.x * blockDim.x + threadIdx.x;
    if (e >= N_EDGES) return;
    int d = g_dst[e];
    int p = atomicAdd(&g_cursor[d], 1);
    g_srcS[p] = g_src[e];
    g_ewS[p] = g_ew[e];
}

// ---------------- gather-aggregate: out[i] = sum_{e: dst=i} in[src_e] * w_e --
template <int C, bool USE_W>
__global__ void gather_kernel(const float* __restrict__ in,
                              float* __restrict__ out) {
    constexpr int L = C / 4;        // lanes per node
    constexpr int G = 256 / L;      // nodes per 256-thread block
    int grp  = threadIdx.x / L;
    int lane = threadIdx.x % L;
    int node = blockIdx.x * G + grp;
    if (node >= N_NODES) return;

    int e0 = g_rowoff[node];
    int e1 = g_rowoff[node + 1];
    const float4* in4 = (const float4*)in;
    float4 acc = make_float4(0.f, 0.f, 0.f, 0.f);

    int e = e0;
    for (; e + 4 <= e1; e += 4) {
        int s0 = g_srcS[e], s1 = g_srcS[e + 1];
        int s2 = g_srcS[e + 2], s3 = g_srcS[e + 3];
        float w0 = USE_W ? g_ewS[e] : 1.0f;
        float w1 = USE_W ? g_ewS[e + 1] : 1.0f;
        float w2 = USE_W ? g_ewS[e + 2] : 1.0f;
        float w3 = USE_W ? g_ewS[e + 3] : 1.0f;
        float4 v0 = in4[(size_t)s0 * L + lane];
        float4 v1 = in4[(size_t)s1 * L + lane];
        float4 v2 = in4[(size_t)s2 * L + lane];
        float4 v3 = in4[(size_t)s3 * L + lane];
        acc.x = fmaf(v0.x, w0, acc.x); acc.y = fmaf(v0.y, w0, acc.y);
        acc.z = fmaf(v0.z, w0, acc.z); acc.w = fmaf(v0.w, w0, acc.w);
        acc.x = fmaf(v1.x, w1, acc.x); acc.y = fmaf(v1.y, w1, acc.y);
        acc.z = fmaf(v1.z, w1, acc.z); acc.w = fmaf(v1.w, w1, acc.w);
        acc.x = fmaf(v2.x, w2, acc.x); acc.y = fmaf(v2.y, w2, acc.y);
        acc.z = fmaf(v2.z, w2, acc.z); acc.w = fmaf(v2.w, w2, acc.w);
        acc.x = fmaf(v3.x, w3, acc.x); acc.y = fmaf(v3.y, w3, acc.y);
        acc.z = fmaf(v3.z, w3, acc.z); acc.w = fmaf(v3.w, w3, acc.w);
    }
    for (; e < e1; e++) {
        int sa = g_srcS[e];
        float wa = USE_W ? g_ewS[e] : 1.0f;
        float4 va = in4[(size_t)sa * L + lane];
        acc.x = fmaf(va.x, wa, acc.x); acc.y = fmaf(va.y, wa, acc.y);
        acc.z = fmaf(va.z, wa, acc.z); acc.w = fmaf(va.w, wa, acc.w);
    }
    ((float4*)out)[(size_t)node * L + lane] = acc;
}

// ---------------- GEMM: out[M,256] = A[M,K] @ W[256,K]^T + epilogue ---------
// BM=BN=64, BK=16, 256 threads, 4x4 register tile per thread. (round-1 proven)
template <int K, bool BN_RELU>
__global__ void gemm_kernel(const float* __restrict__ A,
                            const float* __restrict__ W,
                            const float* __restrict__ bias,
                            const float* __restrict__ gam,
                            const float* __restrict__ bet,
                            const float* __restrict__ mu,
                            const float* __restrict__ var,
                            float* __restrict__ out) {
    constexpr int BM = 64, BN = 64, BK = 16;
    __shared__ float As[BK][BM];
    __shared__ float Bs[BK][BN];

    int m0 = blockIdx.x * BM;
    int n0 = blockIdx.y * BN;
    int tid = threadIdx.x;
    int tx = tid % 16;   // output col group
    int ty = tid / 16;   // output row group

    int lr = tid / 4;          // 0..63 : tile row (A) / weight row n (B)
    int lk = (tid % 4) * 4;    // 0,4,8,12 : k offset

    float acc[4][4];
#pragma unroll
    for (int i = 0; i < 4; i++)
#pragma unroll
        for (int j = 0; j < 4; j++) acc[i][j] = 0.f;

    for (int k0 = 0; k0 < K; k0 += BK) {
        {
            int row = m0 + lr;
            float4 v = make_float4(0.f, 0.f, 0.f, 0.f);
            if (row < N_NODES)
                v = *(const float4*)(A + (size_t)row * K + k0 + lk);
            As[lk + 0][lr] = v.x;
            As[lk + 1][lr] = v.y;
            As[lk + 2][lr] = v.z;
            As[lk + 3][lr] = v.w;

            float4 w = *(const float4*)(W + (size_t)(n0 + lr) * K + k0 + lk);
            Bs[lk + 0][lr] = w.x;
            Bs[lk + 1][lr] = w.y;
            Bs[lk + 2][lr] = w.z;
            Bs[lk + 3][lr] = w.w;
        }
        __syncthreads();
#pragma unroll
        for (int k = 0; k < BK; k++) {
            float4 a = *(const float4*)&As[k][ty * 4];
            float4 b = *(const float4*)&Bs[k][tx * 4];
            float ar[4] = {a.x, a.y, a.z, a.w};
            float br[4] = {b.x, b.y, b.z, b.w};
#pragma unroll
            for (int i = 0; i < 4; i++)
#pragma unroll
                for (int j = 0; j < 4; j++)
                    acc[i][j] = fmaf(ar[i], br[j], acc[i][j]);
        }
        __syncthreads();
    }

    // epilogue: +bias, optional BN(eval)+ReLU, float4 store
    int nbase = n0 + tx * 4;
    float bb[4], ss[4], tt[4];
#pragma unroll
    for (int j = 0; j < 4; j++) {
        bb[j] = bias[nbase + j];
        if (BN_RELU) {
            float inv = gam[nbase + j] * rsqrtf(var[nbase + j] + 1e-5f);
            ss[j] = inv;
            tt[j] = bet[nbase + j] - mu[nbase + j] * inv;
        }
    }
#pragma unroll
    for (int i = 0; i < 4; i++) {
        int m = m0 + ty * 4 + i;
        if (m < N_NODES) {
            float z[4];
#pragma unroll
            for (int j = 0; j < 4; j++) {
                float v = acc[i][j] + bb[j];
                if (BN_RELU) v = fmaxf(fmaf(v, ss[j], tt[j]), 0.f);
                z[j] = v;
            }
            *(float4*)(out + (size_t)m * C_OUT + nbase) =
                make_float4(z[0], z[1], z[2], z[3]);
        }
    }
}

// ---------------- launch ----------------------------------------------------
extern "C" void kernel_launch(void* const* d_in, const int* in_sizes, int n_in,
                              void* d_out, int out_size) {
    const float* x   = (const float*)d_in[0];
    const int*   ei  = (const int*)d_in[1];
    const float* ea  = (const float*)d_in[2];
    const float* W1  = (const float*)d_in[3];
    const float* b1  = (const float*)d_in[4];
    const float* g1  = (const float*)d_in[5];
    const float* be1 = (const float*)d_in[6];
    const float* m1  = (const float*)d_in[7];
    const float* v1  = (const float*)d_in[8];
    const float* W2  = (const float*)d_in[9];
    const float* b2  = (const float*)d_in[10];
    const float* g2  = (const float*)d_in[11];
    const float* be2 = (const float*)d_in[12];
    const float* m2  = (const float*)d_in[13];
    const float* v2  = (const float*)d_in[14];
    const float* W3  = (const float*)d_in[15];
    const float* b3  = (const float*)d_in[16];
    float* out = (float*)d_out;

    void *p_agg, *p_h, *p_deg;
    cudaGetSymbolAddress(&p_agg, g_agg);
    cudaGetSymbolAddress(&p_h, g_h);
    cudaGetSymbolAddress(&p_deg, g_deg);
    float* agg = (float*)p_agg;
    float* h   = (float*)p_h;

    // ---- CSR build (once, reused by all 3 layers) ----
    detect_kernel<<<1, 64>>>(ei);
    cudaMemsetAsync(p_deg, 0, N_NODES * sizeof(int));
    build_edges_kernel<<<(N_EDGES + 255) / 256, 256>>>(ei, ea);
    scan_p1_kernel<<<SCAN_BLOCKS, 256>>>();
    scan_p2_kernel<<<1, 256>>>();
    scan_p3_kernel<<<SCAN_BLOCKS, 256>>>();
    fill_kernel<<<(N_EDGES + 255) / 256, 256>>>();

    dim3 ggrid(782, 4);  // ceil(50000/64) x (256/64), BM=BN=64

    // ---- layer 1: aggregate x (C=128), GEMM K=128 + BN1 + ReLU ----
    gather_kernel<128, true><<<(N_NODES + 7) / 8, 256>>>(x, agg);
    gemm_kernel<128, true><<<ggrid, 256>>>(agg, W1, b1, g1, be1, m1, v1, h);

    // ---- layer 2: aggregate h (C=256), GEMM K=256 + BN2 + ReLU ----
    gather_kernel<256, true><<<(N_NODES + 3) / 4, 256>>>(h, agg);
    gemm_kernel<256, true><<<ggrid, 256>>>(agg, W2, b2, g2, be2, m2, v2, h);

    // ---- layer 3: aggregate h (C=256, no edge weight), GEMM K=256 + bias ----
    gather_kernel<256, false><<<(N_NODES + 3) / 4, 256>>>(h, agg);
    gemm_kernel<256, false><<<ggrid, 256>>>(agg, W3, b3, nullptr, nullptr,
                                            nullptr, nullptr, out);
}